// round 14
// baseline (speedup 1.0000x reference)
#include <cuda_runtime.h>
#include <cuda_fp16.h>
#include <cuda_pipeline.h>
#include <mma.h>

using namespace nvcuda;

#define B_    4
#define N_    2048
#define KC_   2048
#define D_    1024
#define H_    16
#define HD_   64
#define MROWS 8192
#define OUT_ELEMS (MROWS * D_)

// -------------------- device scratch (static; no allocation) --------------------
__device__ __half g_xh   [MROWS * D_];
__device__ __half g_ctxnh[MROWS * D_];
__device__ __half g_qwh  [D_ * D_];
__device__ __half g_kvwh [D_ * 2 * D_];
__device__ __half g_pwh  [D_ * D_];
__device__ __half g_qh   [MROWS * D_];
__device__ __half g_kvh  [MROWS * 2 * D_];
__device__ __half g_oh   [MROWS * D_];

// -------------------- elementwise --------------------
__global__ void f2h_kernel(const float4* __restrict__ src, __half2* __restrict__ dst, int n4) {
    int i = blockIdx.x * 256 + threadIdx.x;
    if (i < n4) {
        float4 v = src[i];
        dst[2 * i]     = __floats2half2_rn(v.x, v.y);
        dst[2 * i + 1] = __floats2half2_rn(v.z, v.w);
    }
}

__global__ void tail_fill_kernel(float* __restrict__ out, int start, int end, float val) {
    int i = start + blockIdx.x * 256 + threadIdx.x;
    if (i < end) out[i] = val;
}

// -------------------- rmsnorm(ctx) -> fp16 --------------------
__global__ void rmsnorm_kernel(const float* __restrict__ ctx) {
    __shared__ float red[8];
    int row = blockIdx.x;
    int tid = threadIdx.x;
    float4 v = reinterpret_cast<const float4*>(ctx + (size_t)row * D_)[tid];
    float s = v.x * v.x + v.y * v.y + v.z * v.z + v.w * v.w;
    #pragma unroll
    for (int o = 16; o; o >>= 1) s += __shfl_xor_sync(0xffffffffu, s, o);
    if ((tid & 31) == 0) red[tid >> 5] = s;
    __syncthreads();
    if (tid < 8) {
        float t = red[tid];
        #pragma unroll
        for (int o = 4; o; o >>= 1) t += __shfl_xor_sync(0xffu, t, o);
        if (tid == 0) red[0] = t;
    }
    __syncthreads();
    float inv = rsqrtf(red[0] * (1.0f / 1024.0f) + 1e-6f);
    __half2* d = reinterpret_cast<__half2*>(g_ctxnh + (size_t)row * D_);
    d[2 * tid]     = __floats2half2_rn(v.x * inv, v.y * inv);
    d[2 * tid + 1] = __floats2half2_rn(v.z * inv, v.w * inv);
}

// -------------------- pipelined wmma GEMM (R11: 32x64 warp tiles, 3-stage) ---------
// block tile 128x128, 256 threads = 8 warps (4x2), warp tile 32x64, K-chunk 32.
// smem (dynamic): As 3 x 128 x 40 half (30720 B), Bs 3 x 32 x 136 half (26112 B).
#define GEMM_SMEM (30720 + 26112)

__device__ __forceinline__ void gemm_core(const __half* __restrict__ A,
                                          const __half* __restrict__ Bm,
                                          const float* __restrict__ bias,
                                          float* __restrict__ Cf,
                                          __half* __restrict__ Ch,
                                          int N, int K, int half_out) {
    extern __shared__ __align__(16) char gsm[];
    __half* As = reinterpret_cast<__half*>(gsm);            // stage stride 5120 halves
    __half* Bs = reinterpret_cast<__half*>(gsm + 30720);    // stage stride 4352 halves

    const int bm = blockIdx.y * 128;
    const int bn = blockIdx.x * 128;
    const int tid = threadIdx.x;
    const int warp = tid >> 5;
    const int lane = tid & 31;
    const int wm = warp >> 1;   // 0..3 : 32-row block
    const int wn = warp & 1;    // 0..1 : 64-col block

    wmma::fragment<wmma::accumulator, 16, 16, 16, float> acc[2][4];
    #pragma unroll
    for (int m = 0; m < 2; m++) {
        #pragma unroll
        for (int n = 0; n < 4; n++) {
            wmma::fill_fragment(acc[m][n], 0.0f);
        }
    }

    const int NC = K >> 5;   // chunks of 32

    // prologue: prefetch chunks 0 and 1 into stages 0,1
    #pragma unroll
    for (int pc = 0; pc < 2; pc++) {
        int k0 = pc << 5;
        #pragma unroll
        for (int rep = 0; rep < 2; rep++) {
            int i = tid + rep * 256;
            int r = i >> 2;
            int c = (i & 3) * 8;
            __pipeline_memcpy_async(As + pc * 5120 + r * 40 + c,
                                    &A[(size_t)(bm + r) * K + k0 + c], 16);
            int rb = i >> 4;
            int cb = (i & 15) * 8;
            __pipeline_memcpy_async(Bs + pc * 4352 + rb * 136 + cb,
                                    &Bm[(size_t)(k0 + rb) * N + bn + cb], 16);
        }
        __pipeline_commit();
    }

    for (int cix = 0; cix < NC; cix++) {
        if (cix + 1 < NC) {
            __pipeline_wait_prior(1);
        } else {
            __pipeline_wait_prior(0);
        }
        __syncthreads();
        if (cix + 2 < NC) {
            int st = (cix + 2) % 3;
            int k0 = (cix + 2) << 5;
            #pragma unroll
            for (int rep = 0; rep < 2; rep++) {
                int i = tid + rep * 256;
                int r = i >> 2;
                int c = (i & 3) * 8;
                __pipeline_memcpy_async(As + st * 5120 + r * 40 + c,
                                        &A[(size_t)(bm + r) * K + k0 + c], 16);
                int rb = i >> 4;
                int cb = (i & 15) * 8;
                __pipeline_memcpy_async(Bs + st * 4352 + rb * 136 + cb,
                                        &Bm[(size_t)(k0 + rb) * N + bn + cb], 16);
            }
            __pipeline_commit();
        }
        int s = cix % 3;
        const __half* Ab = As + s * 5120;
        const __half* Bb = Bs + s * 4352;
        #pragma unroll
        for (int kk = 0; kk < 2; kk++) {
            wmma::fragment<wmma::matrix_a, 16, 16, 16, __half, wmma::row_major> af[2];
            wmma::fragment<wmma::matrix_b, 16, 16, 16, __half, wmma::row_major> bf[4];
            #pragma unroll
            for (int m = 0; m < 2; m++) {
                wmma::load_matrix_sync(af[m], Ab + (wm * 32 + m * 16) * 40 + kk * 16, 40);
            }
            #pragma unroll
            for (int n = 0; n < 4; n++) {
                wmma::load_matrix_sync(bf[n], Bb + (kk * 16) * 136 + wn * 64 + n * 16, 136);
            }
            #pragma unroll
            for (int m = 0; m < 2; m++) {
                #pragma unroll
                for (int n = 0; n < 4; n++) {
                    wmma::mma_sync(acc[m][n], af[m], bf[n], acc[m][n]);
                }
            }
        }
    }
    __syncthreads();

    // fused bias (+convert) epilogue through per-warp 16x20 float staging
    float* stg = reinterpret_cast<float*>(gsm) + warp * 320;
    #pragma unroll
    for (int m = 0; m < 2; m++) {
        #pragma unroll
        for (int n = 0; n < 4; n++) {
            wmma::store_matrix_sync(stg, acc[m][n], 20, wmma::mem_row_major);
            __syncwarp();
            int row = lane >> 1;
            int c0 = (lane & 1) * 8;
            int gr = bm + wm * 32 + m * 16 + row;
            int gc = bn + wn * 64 + n * 16 + c0;
            float4 b0 = *reinterpret_cast<const float4*>(&bias[gc]);
            float4 b1 = *reinterpret_cast<const float4*>(&bias[gc + 4]);
            const float* sp = stg + row * 20 + c0;
            if (half_out) {
                __half2 hv[4];
                hv[0] = __floats2half2_rn(sp[0] + b0.x, sp[1] + b0.y);
                hv[1] = __floats2half2_rn(sp[2] + b0.z, sp[3] + b0.w);
                hv[2] = __floats2half2_rn(sp[4] + b1.x, sp[5] + b1.y);
                hv[3] = __floats2half2_rn(sp[6] + b1.z, sp[7] + b1.w);
                *reinterpret_cast<uint4*>(&Ch[(size_t)gr * N + gc]) =
                    *reinterpret_cast<uint4*>(hv);
            } else {
                float4 o0 = make_float4(sp[0] + b0.x, sp[1] + b0.y, sp[2] + b0.z, sp[3] + b0.w);
                float4 o1 = make_float4(sp[4] + b1.x, sp[5] + b1.y, sp[6] + b1.z, sp[7] + b1.w);
                *reinterpret_cast<float4*>(&Cf[(size_t)gr * N + gc]) = o0;
                *reinterpret_cast<float4*>(&Cf[(size_t)gr * N + gc + 4]) = o1;
            }
            __syncwarp();
        }
    }
}

__global__ void __launch_bounds__(256) gemm_q_kernel(const float* qb) {
    gemm_core(g_xh, g_qwh, qb, 0, g_qh, 1024, 1024, 1);
}
__global__ void __launch_bounds__(256) gemm_kv_kernel(const float* kvb) {
    gemm_core(g_ctxnh, g_kvwh, kvb, 0, g_kvh, 2048, 1024, 1);
}
__global__ void __launch_bounds__(256) gemm_proj_kernel(const float* pb, float* out) {
    gemm_core(g_oh, g_pwh, pb, out, 0, 1024, 1024, 0);
}

// -------------------- flash attention: Q=128/block, in-register softmax -------------
// grid (N/128, H, B), 256 threads = 8 warps; warp w owns query rows [16w, 16w+16).
// Logits clipped to [-10,10] -> fixed-offset softmax: no max tracking; O stays in
// wmma accumulators for the entire KV loop.
// This round: exp applied elementwise IN-REGISTER on the fp32 S accumulator
// fragments, converted elementwise to a half accumulator fragment (same m16n16k16
// accumulator layout) and stored once to Ps — the fp32 staging round-trip is gone.
// Row sums are accumulated on the tensor pipe via a persistent rsum fragment:
// rsum += P x ones(16x16), read back once in the epilogue.
// smem layout (dynamic, 102400 B):
//   Qs  [0,18432)        128 x 72 half
//   Ks  [18432,46080)    3 stages x 64 x 72 half
//   Vs  [46080,73728)    3 stages x 64 x 72 half
//   Ps  [73728,92160)    128 x 72 half      (P tile, warp-private rows)
//   stg [92160,102400)   8 warps x 16 x 20 float (epilogue staging only)
#define FLASH_SMEM 102400

__global__ void __launch_bounds__(256, 2) flash_kernel() {
    extern __shared__ __align__(16) char fsm[];
    __half* Qs = reinterpret_cast<__half*>(fsm);
    __half* Ks = reinterpret_cast<__half*>(fsm + 18432);
    __half* Vs = reinterpret_cast<__half*>(fsm + 46080);
    __half* Ps = reinterpret_cast<__half*>(fsm + 73728);
    float*  stg = reinterpret_cast<float*>(fsm + 92160);

    const int b = blockIdx.z;
    const int h = blockIdx.y;
    const int n0 = blockIdx.x * 128;
    const int tid = threadIdx.x;
    const int warp = tid >> 5;
    const int lane = tid & 31;
    const int rowl = lane >> 1;        // 0..15 : row within warp tile
    const int c0l = (lane & 1) * 8;    // 0 or 8 : col segment

    // group 0: Q tile (128 rows x 64 halves)
    #pragma unroll
    for (int rep = 0; rep < 4; rep++) {
        int i = tid + rep * 256;
        int r = i >> 3;
        int sg = i & 7;
        __pipeline_memcpy_async(Qs + r * 72 + sg * 8,
                                &g_qh[(size_t)(b * N_ + n0 + r) * D_ + h * HD_ + sg * 8], 16);
    }
    __pipeline_commit();

    // groups 1,2: KV chunks 0 and 1 into stages 0,1
    #pragma unroll
    for (int pc = 0; pc < 2; pc++) {
        int kc0 = pc * 64;
        #pragma unroll
        for (int rep = 0; rep < 2; rep++) {
            int i = tid + rep * 256;
            int r = i >> 3;
            int sg = i & 7;
            size_t base = (size_t)(b * KC_ + kc0 + r) * (2 * D_) + h * HD_ + sg * 8;
            __pipeline_memcpy_async(Ks + pc * 4608 + r * 72 + sg * 8, &g_kvh[base], 16);
            __pipeline_memcpy_async(Vs + pc * 4608 + r * 72 + sg * 8, &g_kvh[base + D_], 16);
        }
        __pipeline_commit();
    }

    wmma::fragment<wmma::accumulator, 16, 16, 16, float> oacc[4];
    #pragma unroll
    for (int d = 0; d < 4; d++) {
        wmma::fill_fragment(oacc[d], 0.0f);
    }
    // persistent row-sum accumulator: rsum += P x ones  (every column = row sum)
    wmma::fragment<wmma::accumulator, 16, 16, 16, float> rsum;
    wmma::fill_fragment(rsum, 0.0f);
    wmma::fragment<wmma::matrix_b, 16, 16, 16, __half, wmma::row_major> onesf;
    wmma::fill_fragment(onesf, __float2half(1.0f));

    float* stgw = stg + warp * 320;
    const __half* Qw = Qs + (warp * 16) * 72;
    __half* Pw = Ps + (warp * 16) * 72;

    const int NC = KC_ / 64;   // 32
    for (int c = 0; c < NC; c++) {
        if (c + 1 < NC) {
            __pipeline_wait_prior(1);
        } else {
            __pipeline_wait_prior(0);
        }
        __syncthreads();
        if (c + 2 < NC) {
            int st = (c + 2) % 3;
            int kc0 = (c + 2) * 64;
            #pragma unroll
            for (int rep = 0; rep < 2; rep++) {
                int i = tid + rep * 256;
                int r = i >> 3;
                int sg = i & 7;
                size_t base = (size_t)(b * KC_ + kc0 + r) * (2 * D_) + h * HD_ + sg * 8;
                __pipeline_memcpy_async(Ks + st * 4608 + r * 72 + sg * 8, &g_kvh[base], 16);
                __pipeline_memcpy_async(Vs + st * 4608 + r * 72 + sg * 8, &g_kvh[base + D_], 16);
            }
            __pipeline_commit();
        }
        int s = c % 3;
        const __half* Kb = Ks + s * 4608;
        const __half* Vb = Vs + s * 4608;

        // S = Q * K^T  (warp: 16 rows x 64 keys)
        wmma::fragment<wmma::accumulator, 16, 16, 16, float> sfr[4];
        #pragma unroll
        for (int nf = 0; nf < 4; nf++) {
            wmma::fill_fragment(sfr[nf], 0.0f);
        }
        #pragma unroll
        for (int kf = 0; kf < 4; kf++) {
            wmma::fragment<wmma::matrix_a, 16, 16, 16, __half, wmma::row_major> af;
            wmma::load_matrix_sync(af, Qw + kf * 16, 72);
            #pragma unroll
            for (int nf = 0; nf < 4; nf++) {
                wmma::fragment<wmma::matrix_b, 16, 16, 16, __half, wmma::col_major> bf;
                wmma::load_matrix_sync(bf, Kb + (nf * 16) * 72 + kf * 16, 72);
                wmma::mma_sync(sfr[nf], af, bf, sfr[nf]);
            }
        }

        // P = exp(clip(S*scale)): elementwise in-register, convert to half acc
        // fragment (same accumulator layout), store straight to Ps.
        #pragma unroll
        for (int nf = 0; nf < 4; nf++) {
            wmma::fragment<wmma::accumulator, 16, 16, 16, __half> hfr;
            #pragma unroll
            for (int e = 0; e < 8; e++) {
                float v = sfr[nf].x[e] * 0.125f;
                v = fminf(fmaxf(v, -10.0f), 10.0f);
                hfr.x[e] = __float2half(__expf(v));
            }
            wmma::store_matrix_sync(Pw + nf * 16, hfr, 72, wmma::mem_row_major);
        }
        __syncwarp();

        // O += P * V  and  rsum += P * ones   (warp: 16 rows)
        #pragma unroll
        for (int kf = 0; kf < 4; kf++) {
            wmma::fragment<wmma::matrix_a, 16, 16, 16, __half, wmma::row_major> pf;
            wmma::load_matrix_sync(pf, Pw + kf * 16, 72);
            #pragma unroll
            for (int df = 0; df < 4; df++) {
                wmma::fragment<wmma::matrix_b, 16, 16, 16, __half, wmma::row_major> vf;
                wmma::load_matrix_sync(vf, Vb + (kf * 16) * 72 + df * 16, 72);
                wmma::mma_sync(oacc[df], pf, vf, oacc[df]);
            }
            wmma::mma_sync(rsum, pf, onesf, rsum);
        }
    }

    // epilogue: read row sums from rsum fragment (any column), scale, store fp16
    wmma::store_matrix_sync(stgw, rsum, 20, wmma::mem_row_major);
    __syncwarp();
    float inv = 1.0f / stgw[rowl * 20];
    __syncwarp();
    size_t gbase = (size_t)(b * N_ + n0 + warp * 16 + rowl) * D_ + h * HD_;
    #pragma unroll
    for (int df = 0; df < 4; df++) {
        wmma::store_matrix_sync(stgw, oacc[df], 20, wmma::mem_row_major);
        __syncwarp();
        const float* sp = stgw + rowl * 20 + c0l;
        __half2 hv[4];
        #pragma unroll
        for (int j = 0; j < 4; j++) {
            hv[j] = __floats2half2_rn(sp[2 * j] * inv, sp[2 * j + 1] * inv);
        }
        *reinterpret_cast<uint4*>(&g_oh[gbase + df * 16 + c0l]) =
            *reinterpret_cast<uint4*>(hv);
        __syncwarp();
    }
}

// -------------------- host launch --------------------
extern "C" void kernel_launch(void* const* d_in, const int* in_sizes, int n_in,
                              void* d_out, int out_size) {
    const float* x      = (const float*)d_in[0];
    const float* ctx    = (const float*)d_in[1];
    const float* q_w    = (const float*)d_in[2];
    const float* q_b    = (const float*)d_in[3];
    const float* kv_w   = (const float*)d_in[4];
    const float* kv_b   = (const float*)d_in[5];
    const float* proj_w = (const float*)d_in[6];
    const float* proj_b = (const float*)d_in[7];
    float* out = (float*)d_out;

    __half* p_xh = 0;
    __half* p_qwh = 0;
    __half* p_kvwh = 0;
    __half* p_pwh = 0;
    cudaGetSymbolAddress((void**)&p_xh,   g_xh);
    cudaGetSymbolAddress((void**)&p_qwh,  g_qwh);
    cudaGetSymbolAddress((void**)&p_kvwh, g_kvwh);
    cudaGetSymbolAddress((void**)&p_pwh,  g_pwh);

    cudaFuncSetAttribute(gemm_q_kernel,    cudaFuncAttributeMaxDynamicSharedMemorySize, GEMM_SMEM);
    cudaFuncSetAttribute(gemm_kv_kernel,   cudaFuncAttributeMaxDynamicSharedMemorySize, GEMM_SMEM);
    cudaFuncSetAttribute(gemm_proj_kernel, cudaFuncAttributeMaxDynamicSharedMemorySize, GEMM_SMEM);
    cudaFuncSetAttribute(flash_kernel,     cudaFuncAttributeMaxDynamicSharedMemorySize, FLASH_SMEM);

    {
        int n4 = (MROWS * D_) / 4;
        f2h_kernel<<<(n4 + 255) / 256, 256>>>((const float4*)x, (__half2*)p_xh, n4);
    }
    {
        int n4 = (D_ * D_) / 4;
        f2h_kernel<<<(n4 + 255) / 256, 256>>>((const float4*)q_w, (__half2*)p_qwh, n4);
        f2h_kernel<<<(n4 + 255) / 256, 256>>>((const float4*)proj_w, (__half2*)p_pwh, n4);
    }
    {
        int n4 = (D_ * 2 * D_) / 4;
        f2h_kernel<<<(n4 + 255) / 256, 256>>>((const float4*)kv_w, (__half2*)p_kvwh, n4);
    }
    rmsnorm_kernel<<<MROWS, 256>>>(ctx);

    gemm_q_kernel <<<dim3(8, 64),  256, GEMM_SMEM>>>(q_b);
    gemm_kv_kernel<<<dim3(16, 64), 256, GEMM_SMEM>>>(kv_b);

    flash_kernel<<<dim3(N_ / 128, H_, B_), 256, FLASH_SMEM>>>();

    gemm_proj_kernel<<<dim3(8, 64), 256, GEMM_SMEM>>>(proj_b, out);

    // attn.mean() == 1/K exactly (softmax rows sum to 1)
    if (out_size > OUT_ELEMS) {
        int tail = out_size - OUT_ELEMS;
        tail_fill_kernel<<<(tail + 255) / 256, 256>>>(out, OUT_ELEMS, out_size,
                                                      1.0f / (float)KC_);
    }
}

// round 16
// speedup vs baseline: 1.3719x; 1.3719x over previous
#include <cuda_runtime.h>
#include <cuda_fp16.h>
#include <cuda_pipeline.h>
#include <mma.h>

using namespace nvcuda;

#define B_    4
#define N_    2048
#define KC_   2048
#define D_    1024
#define H_    16
#define HD_   64
#define MROWS 8192
#define OUT_ELEMS (MROWS * D_)

// -------------------- device scratch (static; no allocation) --------------------
__device__ __half g_xh   [MROWS * D_];
__device__ __half g_ctxnh[MROWS * D_];
__device__ __half g_qwh  [D_ * D_];
__device__ __half g_kvwh [D_ * 2 * D_];
__device__ __half g_pwh  [D_ * D_];
__device__ __half g_qh   [MROWS * D_];
__device__ __half g_kvh  [MROWS * 2 * D_];
__device__ __half g_oh   [MROWS * D_];

// -------------------- elementwise --------------------
// One launch converts all four fp32->fp16 arrays. Segment sizes in float4 units:
// x 2097152 | q_w 262144 | kv_w 524288 | proj_w 262144  (total 3145728, all
// segment boundaries are multiples of 256 -> no intra-block divergence).
__global__ void f2h4_kernel(const float4* __restrict__ x,  const float4* __restrict__ qw,
                            const float4* __restrict__ kvw, const float4* __restrict__ pw,
                            __half2* __restrict__ dx,  __half2* __restrict__ dqw,
                            __half2* __restrict__ dkvw, __half2* __restrict__ dpw) {
    int i = blockIdx.x * 256 + threadIdx.x;
    const float4* src;
    __half2* dst;
    int off;
    if (i < 2097152) {
        src = x; dst = dx; off = i;
    } else if (i < 2097152 + 262144) {
        src = qw; dst = dqw; off = i - 2097152;
    } else if (i < 2097152 + 262144 + 524288) {
        src = kvw; dst = dkvw; off = i - (2097152 + 262144);
    } else {
        src = pw; dst = dpw; off = i - (2097152 + 262144 + 524288);
    }
    float4 v = src[off];
    dst[2 * off]     = __floats2half2_rn(v.x, v.y);
    dst[2 * off + 1] = __floats2half2_rn(v.z, v.w);
}

__global__ void tail_fill_kernel(float* __restrict__ out, int start, int end, float val) {
    int i = start + blockIdx.x * 256 + threadIdx.x;
    if (i < end) out[i] = val;
}

// -------------------- rmsnorm(ctx) -> fp16 --------------------
__global__ void rmsnorm_kernel(const float* __restrict__ ctx) {
    __shared__ float red[8];
    int row = blockIdx.x;
    int tid = threadIdx.x;
    float4 v = reinterpret_cast<const float4*>(ctx + (size_t)row * D_)[tid];
    float s = v.x * v.x + v.y * v.y + v.z * v.z + v.w * v.w;
    #pragma unroll
    for (int o = 16; o; o >>= 1) s += __shfl_xor_sync(0xffffffffu, s, o);
    if ((tid & 31) == 0) red[tid >> 5] = s;
    __syncthreads();
    if (tid < 8) {
        float t = red[tid];
        #pragma unroll
        for (int o = 4; o; o >>= 1) t += __shfl_xor_sync(0xffu, t, o);
        if (tid == 0) red[0] = t;
    }
    __syncthreads();
    float inv = rsqrtf(red[0] * (1.0f / 1024.0f) + 1e-6f);
    __half2* d = reinterpret_cast<__half2*>(g_ctxnh + (size_t)row * D_);
    d[2 * tid]     = __floats2half2_rn(v.x * inv, v.y * inv);
    d[2 * tid + 1] = __floats2half2_rn(v.z * inv, v.w * inv);
}

// -------------------- pipelined wmma GEMM (R11/R12: 32x64 warp tiles, 3-stage) -----
// block tile 128x128, 256 threads = 8 warps (4x2), warp tile 32x64, K-chunk 32.
// smem (dynamic): As 3 x 128 x 40 half (30720 B), Bs 3 x 32 x 136 half (26112 B).
#define GEMM_SMEM (30720 + 26112)

__device__ __forceinline__ void gemm_core(const __half* __restrict__ A,
                                          const __half* __restrict__ Bm,
                                          const float* __restrict__ bias,
                                          float* __restrict__ Cf,
                                          __half* __restrict__ Ch,
                                          int N, int K, int half_out,
                                          int bm, int bn) {
    extern __shared__ __align__(16) char gsm[];
    __half* As = reinterpret_cast<__half*>(gsm);            // stage stride 5120 halves
    __half* Bs = reinterpret_cast<__half*>(gsm + 30720);    // stage stride 4352 halves

    const int tid = threadIdx.x;
    const int warp = tid >> 5;
    const int lane = tid & 31;
    const int wm = warp >> 1;   // 0..3 : 32-row block
    const int wn = warp & 1;    // 0..1 : 64-col block

    wmma::fragment<wmma::accumulator, 16, 16, 16, float> acc[2][4];
    #pragma unroll
    for (int m = 0; m < 2; m++) {
        #pragma unroll
        for (int n = 0; n < 4; n++) {
            wmma::fill_fragment(acc[m][n], 0.0f);
        }
    }

    const int NC = K >> 5;   // chunks of 32

    // prologue: prefetch chunks 0 and 1 into stages 0,1
    #pragma unroll
    for (int pc = 0; pc < 2; pc++) {
        int k0 = pc << 5;
        #pragma unroll
        for (int rep = 0; rep < 2; rep++) {
            int i = tid + rep * 256;
            int r = i >> 2;
            int c = (i & 3) * 8;
            __pipeline_memcpy_async(As + pc * 5120 + r * 40 + c,
                                    &A[(size_t)(bm + r) * K + k0 + c], 16);
            int rb = i >> 4;
            int cb = (i & 15) * 8;
            __pipeline_memcpy_async(Bs + pc * 4352 + rb * 136 + cb,
                                    &Bm[(size_t)(k0 + rb) * N + bn + cb], 16);
        }
        __pipeline_commit();
    }

    for (int cix = 0; cix < NC; cix++) {
        if (cix + 1 < NC) {
            __pipeline_wait_prior(1);
        } else {
            __pipeline_wait_prior(0);
        }
        __syncthreads();
        if (cix + 2 < NC) {
            int st = (cix + 2) % 3;
            int k0 = (cix + 2) << 5;
            #pragma unroll
            for (int rep = 0; rep < 2; rep++) {
                int i = tid + rep * 256;
                int r = i >> 2;
                int c = (i & 3) * 8;
                __pipeline_memcpy_async(As + st * 5120 + r * 40 + c,
                                        &A[(size_t)(bm + r) * K + k0 + c], 16);
                int rb = i >> 4;
                int cb = (i & 15) * 8;
                __pipeline_memcpy_async(Bs + st * 4352 + rb * 136 + cb,
                                        &Bm[(size_t)(k0 + rb) * N + bn + cb], 16);
            }
            __pipeline_commit();
        }
        int s = cix % 3;
        const __half* Ab = As + s * 5120;
        const __half* Bb = Bs + s * 4352;
        #pragma unroll
        for (int kk = 0; kk < 2; kk++) {
            wmma::fragment<wmma::matrix_a, 16, 16, 16, __half, wmma::row_major> af[2];
            wmma::fragment<wmma::matrix_b, 16, 16, 16, __half, wmma::row_major> bf[4];
            #pragma unroll
            for (int m = 0; m < 2; m++) {
                wmma::load_matrix_sync(af[m], Ab + (wm * 32 + m * 16) * 40 + kk * 16, 40);
            }
            #pragma unroll
            for (int n = 0; n < 4; n++) {
                wmma::load_matrix_sync(bf[n], Bb + (kk * 16) * 136 + wn * 64 + n * 16, 136);
            }
            #pragma unroll
            for (int m = 0; m < 2; m++) {
                #pragma unroll
                for (int n = 0; n < 4; n++) {
                    wmma::mma_sync(acc[m][n], af[m], bf[n], acc[m][n]);
                }
            }
        }
    }
    __syncthreads();

    // fused bias (+convert) epilogue through per-warp 16x20 float staging
    float* stg = reinterpret_cast<float*>(gsm) + warp * 320;
    #pragma unroll
    for (int m = 0; m < 2; m++) {
        #pragma unroll
        for (int n = 0; n < 4; n++) {
            wmma::store_matrix_sync(stg, acc[m][n], 20, wmma::mem_row_major);
            __syncwarp();
            int row = lane >> 1;
            int c0 = (lane & 1) * 8;
            int gr = bm + wm * 32 + m * 16 + row;
            int gc = bn + wn * 64 + n * 16 + c0;
            float4 b0 = *reinterpret_cast<const float4*>(&bias[gc]);
            float4 b1 = *reinterpret_cast<const float4*>(&bias[gc + 4]);
            const float* sp = stg + row * 20 + c0;
            if (half_out) {
                __half2 hv[4];
                hv[0] = __floats2half2_rn(sp[0] + b0.x, sp[1] + b0.y);
                hv[1] = __floats2half2_rn(sp[2] + b0.z, sp[3] + b0.w);
                hv[2] = __floats2half2_rn(sp[4] + b1.x, sp[5] + b1.y);
                hv[3] = __floats2half2_rn(sp[6] + b1.z, sp[7] + b1.w);
                *reinterpret_cast<uint4*>(&Ch[(size_t)gr * N + gc]) =
                    *reinterpret_cast<uint4*>(hv);
            } else {
                float4 o0 = make_float4(sp[0] + b0.x, sp[1] + b0.y, sp[2] + b0.z, sp[3] + b0.w);
                float4 o1 = make_float4(sp[4] + b1.x, sp[5] + b1.y, sp[6] + b1.z, sp[7] + b1.w);
                *reinterpret_cast<float4*>(&Cf[(size_t)gr * N + gc]) = o0;
                *reinterpret_cast<float4*>(&Cf[(size_t)gr * N + gc + 4]) = o1;
            }
            __syncwarp();
        }
    }
}

// merged q + kv projection: grid (24, 64). bx<8 -> q panel, bx>=8 -> kv panel.
__global__ void __launch_bounds__(256) gemm_qkv_kernel(const float* qb, const float* kvb) {
    int bx = blockIdx.x;
    int by = blockIdx.y;
    if (bx < 8) {
        gemm_core(g_xh, g_qwh, qb, 0, g_qh, 1024, 1024, 1, by * 128, bx * 128);
    } else {
        gemm_core(g_ctxnh, g_kvwh, kvb, 0, g_kvh, 2048, 1024, 1, by * 128, (bx - 8) * 128);
    }
}
__global__ void __launch_bounds__(256) gemm_proj_kernel(const float* pb, float* out) {
    gemm_core(g_oh, g_pwh, pb, out, 0, 1024, 1024, 0, blockIdx.y * 128, blockIdx.x * 128);
}

// -------------------- flash attention (R12, unchanged): Q=128/block ----------------
// grid (N/128, H, B), 256 threads = 8 warps; warp w owns query rows [16w, 16w+16).
// Logits clipped to [-10,10] -> fixed-offset softmax: no max tracking; O stays in
// wmma accumulators for the entire KV loop; P rows and row-sums are warp-private
// (registers + warp-local smem), so ONE __syncthreads per 64-key chunk.
// 3-stage KV pipeline via cp.async.
// smem layout (dynamic, 102400 B):
//   Qs  [0,18432)        128 x 72 half
//   Ks  [18432,46080)    3 stages x 64 x 72 half
//   Vs  [46080,73728)    3 stages x 64 x 72 half
//   Ps  [73728,92160)    128 x 72 half      (P tile, warp-private rows)
//   stg [92160,102400)   8 warps x 16 x 20 float
#define FLASH_SMEM 102400

__global__ void __launch_bounds__(256) flash_kernel() {
    extern __shared__ __align__(16) char fsm[];
    __half* Qs = reinterpret_cast<__half*>(fsm);
    __half* Ks = reinterpret_cast<__half*>(fsm + 18432);
    __half* Vs = reinterpret_cast<__half*>(fsm + 46080);
    __half* Ps = reinterpret_cast<__half*>(fsm + 73728);
    float*  stg = reinterpret_cast<float*>(fsm + 92160);

    const int b = blockIdx.z;
    const int h = blockIdx.y;
    const int n0 = blockIdx.x * 128;
    const int tid = threadIdx.x;
    const int warp = tid >> 5;
    const int lane = tid & 31;
    const int rowl = lane >> 1;        // 0..15 : row within warp tile
    const int c0l = (lane & 1) * 8;    // 0 or 8 : col segment

    // group 0: Q tile (128 rows x 64 halves)
    #pragma unroll
    for (int rep = 0; rep < 4; rep++) {
        int i = tid + rep * 256;
        int r = i >> 3;
        int sg = i & 7;
        __pipeline_memcpy_async(Qs + r * 72 + sg * 8,
                                &g_qh[(size_t)(b * N_ + n0 + r) * D_ + h * HD_ + sg * 8], 16);
    }
    __pipeline_commit();

    // groups 1,2: KV chunks 0 and 1 into stages 0,1
    #pragma unroll
    for (int pc = 0; pc < 2; pc++) {
        int kc0 = pc * 64;
        #pragma unroll
        for (int rep = 0; rep < 2; rep++) {
            int i = tid + rep * 256;
            int r = i >> 3;
            int sg = i & 7;
            size_t base = (size_t)(b * KC_ + kc0 + r) * (2 * D_) + h * HD_ + sg * 8;
            __pipeline_memcpy_async(Ks + pc * 4608 + r * 72 + sg * 8, &g_kvh[base], 16);
            __pipeline_memcpy_async(Vs + pc * 4608 + r * 72 + sg * 8, &g_kvh[base + D_], 16);
        }
        __pipeline_commit();
    }

    wmma::fragment<wmma::accumulator, 16, 16, 16, float> oacc[4];
    #pragma unroll
    for (int d = 0; d < 4; d++) {
        wmma::fill_fragment(oacc[d], 0.0f);
    }
    float rowsum = 0.0f;

    float* stgw = stg + warp * 320;
    const __half* Qw = Qs + (warp * 16) * 72;
    __half* Pw = Ps + (warp * 16) * 72;

    const int NC = KC_ / 64;   // 32
    for (int c = 0; c < NC; c++) {
        if (c + 1 < NC) {
            __pipeline_wait_prior(1);
        } else {
            __pipeline_wait_prior(0);
        }
        __syncthreads();
        if (c + 2 < NC) {
            int st = (c + 2) % 3;
            int kc0 = (c + 2) * 64;
            #pragma unroll
            for (int rep = 0; rep < 2; rep++) {
                int i = tid + rep * 256;
                int r = i >> 3;
                int sg = i & 7;
                size_t base = (size_t)(b * KC_ + kc0 + r) * (2 * D_) + h * HD_ + sg * 8;
                __pipeline_memcpy_async(Ks + st * 4608 + r * 72 + sg * 8, &g_kvh[base], 16);
                __pipeline_memcpy_async(Vs + st * 4608 + r * 72 + sg * 8, &g_kvh[base + D_], 16);
            }
            __pipeline_commit();
        }
        int s = c % 3;
        const __half* Kb = Ks + s * 4608;
        const __half* Vb = Vs + s * 4608;

        // S = Q * K^T  (warp: 16 rows x 64 keys)
        wmma::fragment<wmma::accumulator, 16, 16, 16, float> sfr[4];
        #pragma unroll
        for (int nf = 0; nf < 4; nf++) {
            wmma::fill_fragment(sfr[nf], 0.0f);
        }
        #pragma unroll
        for (int kf = 0; kf < 4; kf++) {
            wmma::fragment<wmma::matrix_a, 16, 16, 16, __half, wmma::row_major> af;
            wmma::load_matrix_sync(af, Qw + kf * 16, 72);
            #pragma unroll
            for (int nf = 0; nf < 4; nf++) {
                wmma::fragment<wmma::matrix_b, 16, 16, 16, __half, wmma::col_major> bf;
                wmma::load_matrix_sync(bf, Kb + (nf * 16) * 72 + kf * 16, 72);
                wmma::mma_sync(sfr[nf], af, bf, sfr[nf]);
            }
        }

        // P = exp(clip(S*scale)) -> Ps (warp-private rows); row sums in registers
        #pragma unroll
        for (int nf = 0; nf < 4; nf++) {
            wmma::store_matrix_sync(stgw, sfr[nf], 20, wmma::mem_row_major);
            __syncwarp();
            const float* sp = stgw + rowl * 20 + c0l;
            __half2* pp = reinterpret_cast<__half2*>(Pw + rowl * 72 + nf * 16 + c0l);
            #pragma unroll
            for (int j = 0; j < 4; j++) {
                float a = fminf(fmaxf(sp[2 * j] * 0.125f, -10.0f), 10.0f);
                float d2 = fminf(fmaxf(sp[2 * j + 1] * 0.125f, -10.0f), 10.0f);
                a = __expf(a);
                d2 = __expf(d2);
                rowsum += a + d2;
                pp[j] = __floats2half2_rn(a, d2);
            }
            __syncwarp();
        }

        // O += P * V  (warp: 16 rows x 64 d-cols)
        #pragma unroll
        for (int kf = 0; kf < 4; kf++) {
            wmma::fragment<wmma::matrix_a, 16, 16, 16, __half, wmma::row_major> pf;
            wmma::load_matrix_sync(pf, Pw + kf * 16, 72);
            #pragma unroll
            for (int df = 0; df < 4; df++) {
                wmma::fragment<wmma::matrix_b, 16, 16, 16, __half, wmma::row_major> vf;
                wmma::load_matrix_sync(vf, Vb + (kf * 16) * 72 + df * 16, 72);
                wmma::mma_sync(oacc[df], pf, vf, oacc[df]);
            }
        }
    }

    // epilogue: combine pair row sums, scale, store fp16
    float tot = rowsum + __shfl_xor_sync(0xffffffffu, rowsum, 1);
    float inv = 1.0f / tot;
    size_t gbase = (size_t)(b * N_ + n0 + warp * 16 + rowl) * D_ + h * HD_;
    #pragma unroll
    for (int df = 0; df < 4; df++) {
        wmma::store_matrix_sync(stgw, oacc[df], 20, wmma::mem_row_major);
        __syncwarp();
        const float* sp = stgw + rowl * 20 + c0l;
        __half2 hv[4];
        #pragma unroll
        for (int j = 0; j < 4; j++) {
            hv[j] = __floats2half2_rn(sp[2 * j] * inv, sp[2 * j + 1] * inv);
        }
        *reinterpret_cast<uint4*>(&g_oh[gbase + df * 16 + c0l]) =
            *reinterpret_cast<uint4*>(hv);
        __syncwarp();
    }
}

// -------------------- host launch --------------------
extern "C" void kernel_launch(void* const* d_in, const int* in_sizes, int n_in,
                              void* d_out, int out_size) {
    const float* x      = (const float*)d_in[0];
    const float* ctx    = (const float*)d_in[1];
    const float* q_w    = (const float*)d_in[2];
    const float* q_b    = (const float*)d_in[3];
    const float* kv_w   = (const float*)d_in[4];
    const float* kv_b   = (const float*)d_in[5];
    const float* proj_w = (const float*)d_in[6];
    const float* proj_b = (const float*)d_in[7];
    float* out = (float*)d_out;

    __half* p_xh = 0;
    __half* p_qwh = 0;
    __half* p_kvwh = 0;
    __half* p_pwh = 0;
    cudaGetSymbolAddress((void**)&p_xh,   g_xh);
    cudaGetSymbolAddress((void**)&p_qwh,  g_qwh);
    cudaGetSymbolAddress((void**)&p_kvwh, g_kvwh);
    cudaGetSymbolAddress((void**)&p_pwh,  g_pwh);

    cudaFuncSetAttribute(gemm_qkv_kernel,  cudaFuncAttributeMaxDynamicSharedMemorySize, GEMM_SMEM);
    cudaFuncSetAttribute(gemm_proj_kernel, cudaFuncAttributeMaxDynamicSharedMemorySize, GEMM_SMEM);
    cudaFuncSetAttribute(flash_kernel,     cudaFuncAttributeMaxDynamicSharedMemorySize, FLASH_SMEM);

    // all fp32->fp16 conversions in one launch (3145728 float4 / 256 = 12288 blocks)
    f2h4_kernel<<<12288, 256>>>((const float4*)x, (const float4*)q_w,
                                (const float4*)kv_w, (const float4*)proj_w,
                                (__half2*)p_xh, (__half2*)p_qwh,
                                (__half2*)p_kvwh, (__half2*)p_pwh);

    rmsnorm_kernel<<<MROWS, 256>>>(ctx);

    gemm_qkv_kernel<<<dim3(24, 64), 256, GEMM_SMEM>>>(q_b, kv_b);

    flash_kernel<<<dim3(N_ / 128, H_, B_), 256, FLASH_SMEM>>>();

    gemm_proj_kernel<<<dim3(8, 64), 256, GEMM_SMEM>>>(proj_b, out);

    // attn.mean() == 1/K exactly (softmax rows sum to 1)
    if (out_size > OUT_ELEMS) {
        int tail = out_size - OUT_ELEMS;
        tail_fill_kernel<<<(tail + 255) / 256, 256>>>(out, OUT_ELEMS, out_size,
                                                      1.0f / (float)KC_);
    }
}